// round 1
// baseline (speedup 1.0000x reference)
#include <cuda_runtime.h>

#define NB   4
#define DC   256
#define HH   64
#define WW   64
#define HW   4096
#define DCH  8       // chunks over D
#define DPER 32      // D per chunk
#define NOFF 12      // 9 window offsets + 3 extra agg offsets

// offset order: 3x3 window row-major (index 4 = (0,0)), then (-1,2),(2,-1),(2,2).
// agg offsets are {(-1,-1),(-1,2),(2,-1),(2,2)} = indices {0,9,10,11}.
__device__ __constant__ int c_dy[NOFF] = {-1,-1,-1, 0,0,0, 1,1,1, -1, 2, 2};
__device__ __constant__ int c_dx[NOFF] = {-1, 0, 1,-1,0,1,-1,0,1,  2,-1, 2};

// scratch (no allocations allowed): partial sums, weights, cond mask
__device__ float  g_part[(size_t)NB * DCH * 14 * HW];   // [n][chunk][14][pix], ~7.3 MB
__device__ float4 g_w[NB * HW];
__device__ float  g_cond[NB * HW];

// ---------------------------------------------------------------------------
// Pass 1: per-pixel partial sums over a D-chunk:
//   acc[0..11] = sum_d cur[d,q] * prev[d,q+off_k]  (clamped indices; masked later)
//   acc[12]    = sum_d cur[d,q]^2
//   acc[13]    = sum_d prev[d,q]^2
// grid (8 ytiles, 8 dchunks, 4 batch), block (64, 8) -> 256 blocks x 512 thr
// ---------------------------------------------------------------------------
__global__ __launch_bounds__(512) void k_partial(const float* __restrict__ cur,
                                                 const float* __restrict__ prev) {
    const int x   = threadIdx.x;                       // 0..63
    const int y   = blockIdx.x * blockDim.y + threadIdx.y;
    const int dch = blockIdx.y;
    const int n   = blockIdx.z;
    const int pix = y * WW + x;

    const float* curB  = cur  + (size_t)n * DC * HW;
    const float* prevB = prev + (size_t)n * DC * HW;

    int nbr[NOFF];
#pragma unroll
    for (int k = 0; k < NOFF; k++) {
        int py = y + c_dy[k]; py = py < 0 ? 0 : (py > HH - 1 ? HH - 1 : py);
        int px = x + c_dx[k]; px = px < 0 ? 0 : (px > WW - 1 ? WW - 1 : px);
        nbr[k] = py * WW + px;
    }

    float acc[14];
#pragma unroll
    for (int k = 0; k < 14; k++) acc[k] = 0.f;

    const int d0 = dch * DPER;
#pragma unroll 2
    for (int dd = 0; dd < DPER; dd++) {
        const float* cp = curB  + (size_t)(d0 + dd) * HW;
        const float* pp = prevB + (size_t)(d0 + dd) * HW;
        const float c = __ldg(cp + pix);
        float pv[NOFF];
#pragma unroll
        for (int k = 0; k < NOFF; k++) pv[k] = __ldg(pp + nbr[k]);
#pragma unroll
        for (int k = 0; k < NOFF; k++) acc[k] = fmaf(c, pv[k], acc[k]);
        acc[12] = fmaf(c, c, acc[12]);
        acc[13] = fmaf(pv[4], pv[4], acc[13]);   // pv[4] = prev at (0,0) offset
    }

    float* o = g_part + (size_t)(n * DCH + dch) * 14 * HW + pix;
#pragma unroll
    for (int k = 0; k < 14; k++) o[(size_t)k * HW] = acc[k];
}

// ---------------------------------------------------------------------------
// Pass 2: reduce chunks, normalize to cosine affinity, build mass/cond and the
// 4 aggregation weights per pixel.  16384 threads total.
// ---------------------------------------------------------------------------
__global__ __launch_bounds__(256) void k_weights() {
    const int t   = blockIdx.x * blockDim.x + threadIdx.x;   // 0..NB*HW-1
    const int n   = t >> 12;
    const int pix = t & (HW - 1);
    const int y   = pix >> 6;
    const int x   = pix & (WW - 1);

    const float* base = g_part + (size_t)n * DCH * 14 * HW;

    float acc[14];
#pragma unroll
    for (int k = 0; k < 14; k++) acc[k] = 0.f;
#pragma unroll
    for (int c = 0; c < DCH; c++) {
        const float* b = base + (size_t)c * 14 * HW + pix;
#pragma unroll
        for (int k = 0; k < 14; k++) acc[k] += b[(size_t)k * HW];
    }

    const float cn = sqrtf(acc[12]) + 1e-8f;

    float aff[NOFF];
#pragma unroll
    for (int k = 0; k < NOFF; k++) {
        const int py = y + c_dy[k];
        const int px = x + c_dx[k];
        const bool valid = (py >= 0) & (py < HH) & (px >= 0) & (px < WW);
        int pyc = py < 0 ? 0 : (py > HH - 1 ? HH - 1 : py);
        int pxc = px < 0 ? 0 : (px > WW - 1 ? WW - 1 : px);
        const int np = pyc * WW + pxc;
        // neighbor ||prev|| from the chunk partials (slot 13)
        float pn2 = 0.f;
#pragma unroll
        for (int c = 0; c < DCH; c++)
            pn2 += base[(size_t)c * 14 * HW + (size_t)13 * HW + np];
        const float pn = sqrtf(pn2) + 1e-8f;
        float a = acc[k] / (cn * pn);
        a = fmaxf(a, 0.f);
        aff[k] = valid ? a : 0.f;
    }

    float mass = 0.f;
#pragma unroll
    for (int k = 0; k < 9; k++) mass += aff[k];

    const bool  cond = (mass > -10.f) && (mass < 10.f);
    const float ms   = mass > 0.f ? mass : 1.f;
    const float inv  = 1.f / ms;

    const float w0 = aff[0]  > 0.f ? aff[0]  * inv : 0.f;  // (-1,-1)
    const float w1 = aff[9]  > 0.f ? aff[9]  * inv : 0.f;  // (-1,+2)
    const float w2 = aff[10] > 0.f ? aff[10] * inv : 0.f;  // (+2,-1)
    const float w3 = aff[11] > 0.f ? aff[11] * inv : 0.f;  // (+2,+2)

    g_w[t]    = make_float4(w0, w1, w2, w3);
    g_cond[t] = cond ? 1.f : 0.f;
}

// ---------------------------------------------------------------------------
// Pass 3: out[n,d,y,x] = cond ? mem + (d>0)*sum_k w_k*mem[off_k] : 0
// 4M threads, pure streaming (HBM-bound).
// ---------------------------------------------------------------------------
__global__ __launch_bounds__(256) void k_output(const float* __restrict__ mem,
                                                float* __restrict__ out) {
    const int tid = blockIdx.x * blockDim.x + threadIdx.x;  // 0..NB*DC*HW-1
    const int pix = tid & (HW - 1);
    const int nd  = tid >> 12;
    const int d   = nd & (DC - 1);
    const int n   = nd >> 8;
    const int y   = pix >> 6;
    const int x   = pix & (WW - 1);

    const int    np   = n * HW + pix;
    const float  cond = g_cond[np];
    const float4 w    = g_w[np];

    const float* mp = mem + (size_t)nd * HW;
    float v = mp[pix];
    if (d != 0) {                      // uniform per warp (nd constant in block)
        const int y0 = y - 1 < 0 ? 0 : y - 1;
        const int y1 = y + 2 > HH - 1 ? HH - 1 : y + 2;
        const int x0 = x - 1 < 0 ? 0 : x - 1;
        const int x1 = x + 2 > WW - 1 ? WW - 1 : x + 2;
        v = fmaf(w.x, mp[y0 * WW + x0], v);
        v = fmaf(w.y, mp[y0 * WW + x1], v);
        v = fmaf(w.z, mp[y1 * WW + x0], v);
        v = fmaf(w.w, mp[y1 * WW + x1], v);
    }
    out[tid] = (cond != 0.f) ? v : 0.f;
}

// ---------------------------------------------------------------------------
extern "C" void kernel_launch(void* const* d_in, const int* in_sizes, int n_in,
                              void* d_out, int out_size) {
    const float* cur  = (const float*)d_in[0];
    const float* prev = (const float*)d_in[1];
    const float* mem  = (const float*)d_in[2];
    float* out = (float*)d_out;

    k_partial<<<dim3(HH / 8, DCH, NB), dim3(WW, 8)>>>(cur, prev);
    k_weights<<<(NB * HW) / 256, 256>>>();
    k_output<<<(NB * DC * HW) / 256, 256>>>(mem, out);
}

// round 2
// speedup vs baseline: 1.1468x; 1.1468x over previous
#include <cuda_runtime.h>

#define NB   4
#define DC   256
#define HH   64
#define WW   64
#define HW   4096
#define DCH  8        // chunks over D
#define DPER 32       // D per chunk
#define NOFF 12
#define TY   4        // rows per k_partial/k_weights block
#define HALO 7        // TY + 3 halo rows (dy in -1..2)
#define DSLICE 4      // d-slices staged per sync

// offset order: 3x3 window row-major (idx 4 = (0,0)), then (-1,2),(2,-1),(2,2).
__device__ __constant__ int c_dy[NOFF] = {-1,-1,-1, 0,0,0, 1,1,1, -1, 2, 2};
__device__ __constant__ int c_dx[NOFF] = {-1, 0, 1,-1,0,1,-1,0,1,  2,-1, 2};

// scratch (no allocations allowed)
__device__ float g_part[(size_t)NB * DCH * 14 * HW];   // ~7.3 MB
__device__ float g_w0[NB * HW];
__device__ float g_w1[NB * HW];
__device__ float g_w2[NB * HW];
__device__ float g_w3[NB * HW];
__device__ float g_cond[NB * HW];

__device__ __forceinline__ int iclamp(int v, int lo, int hi) {
    return v < lo ? lo : (v > hi ? hi : v);
}

// ---------------------------------------------------------------------------
// Pass 1: smem-tiled partial dot products over a D-chunk.
// grid (16 ytiles, 8 dchunks, 4 batch) = 512 blocks, block (64, 4) = 256 thr
// smem: DSLICE d-slices x 7 halo rows x 64 cols of prev.
// ---------------------------------------------------------------------------
__global__ __launch_bounds__(256) void k_partial(const float* __restrict__ cur,
                                                 const float* __restrict__ prev) {
    __shared__ float sp[DSLICE * HALO * WW];   // 7168 B

    const int x   = threadIdx.x;
    const int ty  = threadIdx.y;
    const int y0  = blockIdx.x * TY;
    const int dch = blockIdx.y;
    const int n   = blockIdx.z;
    const int tid = ty * WW + x;
    const int y   = y0 + ty;
    const int pix = y * WW + x;

    const float* curB  = cur  + (size_t)n * DC * HW;
    const float* prevB = prev + (size_t)n * DC * HW;

    // clamped column indices (row clamping is baked into the smem stage)
    const int xm  = x - 1 < 0 ? 0 : x - 1;
    const int xp1 = x + 1 > WW - 1 ? WW - 1 : x + 1;
    const int xp2 = x + 2 > WW - 1 ? WW - 1 : x + 2;
    const int rA = (ty    ) * WW;   // dy=-1
    const int rB = (ty + 1) * WW;   // dy= 0
    const int rC = (ty + 2) * WW;   // dy=+1
    const int rD = (ty + 3) * WW;   // dy=+2

    float acc[14];
#pragma unroll
    for (int k = 0; k < 14; k++) acc[k] = 0.f;

    const int d0 = dch * DPER;
#pragma unroll 1
    for (int d4 = 0; d4 < DPER / DSLICE; d4++) {
        const int dbase = d0 + d4 * DSLICE;
        __syncthreads();
        // stage DSLICE*7*64 = 1792 floats with 256 threads (7 each)
#pragma unroll
        for (int j = 0; j < (DSLICE * HALO * WW) / 256; j++) {
            const int i  = tid + j * 256;
            const int s  = i / (HALO * WW);
            const int rm = i - s * (HALO * WW);
            const int r  = rm >> 6;
            const int cc = rm & (WW - 1);
            const int gr = iclamp(y0 - 1 + r, 0, HH - 1);
            sp[i] = __ldg(prevB + (size_t)(dbase + s) * HW + gr * WW + cc);
        }
        __syncthreads();

#pragma unroll
        for (int s = 0; s < DSLICE; s++) {
            const float c = __ldg(curB + (size_t)(dbase + s) * HW + pix);
            const float* P = sp + s * (HALO * WW);
            const float a0  = P[rA + xm];
            const float a1  = P[rA + x];
            const float a2  = P[rA + xp1];
            const float a3  = P[rB + xm];
            const float a4  = P[rB + x];
            const float a5  = P[rB + xp1];
            const float a6  = P[rC + xm];
            const float a7  = P[rC + x];
            const float a8  = P[rC + xp1];
            const float a9  = P[rA + xp2];
            const float a10 = P[rD + xm];
            const float a11 = P[rD + xp2];
            acc[0]  = fmaf(c, a0,  acc[0]);
            acc[1]  = fmaf(c, a1,  acc[1]);
            acc[2]  = fmaf(c, a2,  acc[2]);
            acc[3]  = fmaf(c, a3,  acc[3]);
            acc[4]  = fmaf(c, a4,  acc[4]);
            acc[5]  = fmaf(c, a5,  acc[5]);
            acc[6]  = fmaf(c, a6,  acc[6]);
            acc[7]  = fmaf(c, a7,  acc[7]);
            acc[8]  = fmaf(c, a8,  acc[8]);
            acc[9]  = fmaf(c, a9,  acc[9]);
            acc[10] = fmaf(c, a10, acc[10]);
            acc[11] = fmaf(c, a11, acc[11]);
            acc[12] = fmaf(c, c,   acc[12]);
            acc[13] = fmaf(a4, a4, acc[13]);
        }
    }

    float* o = g_part + (size_t)(n * DCH + dch) * 14 * HW + pix;
#pragma unroll
    for (int k = 0; k < 14; k++) o[(size_t)k * HW] = acc[k];
}

// ---------------------------------------------------------------------------
// Pass 2: reduce chunks -> cosine affinity -> mass/cond + 4 agg weights.
// grid (16, NB), block (64, 4). Neighbor ||prev|| cached in smem.
// ---------------------------------------------------------------------------
__global__ __launch_bounds__(256) void k_weights() {
    __shared__ float s_pn[HALO * WW];

    const int x   = threadIdx.x;
    const int ty  = threadIdx.y;
    const int y0  = blockIdx.x * TY;
    const int n   = blockIdx.y;
    const int tid = ty * WW + x;

    const float* base = g_part + (size_t)n * DCH * 14 * HW;

    // phase A: per-halo-pixel prev-norm (slot 13 over chunks)
    for (int i = tid; i < HALO * WW; i += 256) {
        const int r  = i >> 6;
        const int cc = i & (WW - 1);
        const int gr = iclamp(y0 - 1 + r, 0, HH - 1);
        const int gp = gr * WW + cc;
        float s = 0.f;
#pragma unroll
        for (int c = 0; c < DCH; c++)
            s += base[((size_t)c * 14 + 13) * HW + gp];
        s_pn[i] = sqrtf(s) + 1e-8f;
    }
    __syncthreads();

    const int y   = y0 + ty;
    const int pix = y * WW + x;

    float acc[14];
#pragma unroll
    for (int k = 0; k < 14; k++) acc[k] = 0.f;
#pragma unroll
    for (int c = 0; c < DCH; c++) {
        const float* b = base + (size_t)c * 14 * HW + pix;
#pragma unroll
        for (int k = 0; k < 14; k++) acc[k] += b[(size_t)k * HW];
    }

    const float cn    = sqrtf(acc[12]) + 1e-8f;
    const float invcn = 1.f / cn;

    float aff[NOFF];
#pragma unroll
    for (int k = 0; k < NOFF; k++) {
        const int py = y + c_dy[k];
        const int px = x + c_dx[k];
        const bool valid = (py >= 0) & (py < HH) & (px >= 0) & (px < WW);
        const int lr = ty + c_dy[k] + 1;               // local halo row
        const int lc = iclamp(px, 0, WW - 1);
        const float pn = s_pn[lr * WW + lc];
        float a = acc[k] * invcn / pn;
        a = fmaxf(a, 0.f);
        aff[k] = valid ? a : 0.f;
    }

    float mass = 0.f;
#pragma unroll
    for (int k = 0; k < 9; k++) mass += aff[k];

    const bool  cond = (mass > -10.f) && (mass < 10.f);
    const float ms   = mass > 0.f ? mass : 1.f;
    const float inv  = 1.f / ms;

    const int t = n * HW + pix;
    g_w0[t]   = aff[0]  > 0.f ? aff[0]  * inv : 0.f;  // (-1,-1)
    g_w1[t]   = aff[9]  > 0.f ? aff[9]  * inv : 0.f;  // (-1,+2)
    g_w2[t]   = aff[10] > 0.f ? aff[10] * inv : 0.f;  // (+2,-1)
    g_w3[t]   = aff[11] > 0.f ? aff[11] * inv : 0.f;  // (+2,+2)
    g_cond[t] = cond ? 1.f : 0.f;
}

// ---------------------------------------------------------------------------
// Pass 3: out = cond * (mem + (d>0) * sum_k w_k * mem[off_k]); 4 pixels/thread.
// 1M threads, vectorized float4 path -> DRAM bound.
// ---------------------------------------------------------------------------
__global__ __launch_bounds__(256) void k_output(const float* __restrict__ mem,
                                                float* __restrict__ out) {
    const int tid = blockIdx.x * blockDim.x + threadIdx.x;  // 0..NB*DC*1024-1
    const int pg  = tid & 1023;             // pixel group (4 px) within image
    const int nd  = tid >> 10;              // uniform per block
    const int d   = nd & (DC - 1);
    const int n   = nd >> 8;
    const int y   = pg >> 4;
    const int x0  = (pg & 15) << 2;

    const int np = n * HW + y * WW + x0;
    const float4 cond = *(const float4*)&g_cond[np];
    const float4 w0   = *(const float4*)&g_w0[np];
    const float4 w1   = *(const float4*)&g_w1[np];
    const float4 w2   = *(const float4*)&g_w2[np];
    const float4 w3   = *(const float4*)&g_w3[np];

    const float* mp = mem + (size_t)nd * HW;
    float4 v = *(const float4*)&mp[y * WW + x0];

    if (d != 0) {   // uniform branch per block
        const int ym = y - 1 < 0 ? 0 : y - 1;
        const int yp = y + 2 > HH - 1 ? HH - 1 : y + 2;
        const float* ru = mp + ym * WW;
        const float* rd = mp + yp * WW;

        const float4 Au = *(const float4*)&ru[x0];
        const float4 Ad = *(const float4*)&rd[x0];
        const float Lu = (x0 == 0) ? Au.x : ru[x0 - 1];
        const float Ld = (x0 == 0) ? Ad.x : rd[x0 - 1];
        float2 Ru, Rd;
        if (x0 < WW - 4) {
            Ru = *(const float2*)&ru[x0 + 4];
            Rd = *(const float2*)&rd[x0 + 4];
        } else {              // x0 == 60: cols 64,65 clamp to 63 = A.w
            Ru = make_float2(Au.w, Au.w);
            Rd = make_float2(Ad.w, Ad.w);
        }

        // per-pixel p: xm value = (p==0 ? L : A[p-1]); xp value =
        //   p=0->A.z, p=1->A.w, p=2->R.x, p=3->R.y
        v.x = fmaf(w0.x, Lu,   fmaf(w1.x, Au.z, fmaf(w2.x, Ld,   fmaf(w3.x, Ad.z, v.x))));
        v.y = fmaf(w0.y, Au.x, fmaf(w1.y, Au.w, fmaf(w2.y, Ad.x, fmaf(w3.y, Ad.w, v.y))));
        v.z = fmaf(w0.z, Au.y, fmaf(w1.z, Ru.x, fmaf(w2.z, Ad.y, fmaf(w3.z, Rd.x, v.z))));
        v.w = fmaf(w0.w, Au.z, fmaf(w1.w, Ru.y, fmaf(w2.w, Ad.z, fmaf(w3.w, Rd.y, v.w))));
    }

    v.x = cond.x != 0.f ? v.x : 0.f;
    v.y = cond.y != 0.f ? v.y : 0.f;
    v.z = cond.z != 0.f ? v.z : 0.f;
    v.w = cond.w != 0.f ? v.w : 0.f;

    *(float4*)&out[(size_t)nd * HW + y * WW + x0] = v;
}

// ---------------------------------------------------------------------------
extern "C" void kernel_launch(void* const* d_in, const int* in_sizes, int n_in,
                              void* d_out, int out_size) {
    const float* cur  = (const float*)d_in[0];
    const float* prev = (const float*)d_in[1];
    const float* mem  = (const float*)d_in[2];
    float* out = (float*)d_out;

    k_partial<<<dim3(HH / TY, DCH, NB), dim3(WW, TY)>>>(cur, prev);
    k_weights<<<dim3(HH / TY, NB), dim3(WW, TY)>>>();
    k_output<<<(NB * DC * HW / 4) / 256, 256>>>(mem, out);
}

// round 3
// speedup vs baseline: 1.2601x; 1.0989x over previous
#include <cuda_runtime.h>

#define NB   4
#define DC   256
#define HH   64
#define WW   64
#define HW   4096
#define DCH  8        // chunks over D
#define DPER 32       // D per chunk
#define NOFF 12
#define TY   4        // rows per k_partial/k_weights block
#define HALO 7        // TY + 3 halo rows (dy in -1..2)
#define DSLICE 4      // d-slices per pipeline stage

// offset order: 3x3 window row-major (idx 4 = (0,0)), then (-1,2),(2,-1),(2,2).
__device__ __constant__ int c_dy[NOFF] = {-1,-1,-1, 0,0,0, 1,1,1, -1, 2, 2};
__device__ __constant__ int c_dx[NOFF] = {-1, 0, 1,-1,0,1,-1,0,1,  2,-1, 2};

// scratch (no allocations allowed)
__device__ float g_part[(size_t)NB * DCH * 14 * HW];   // [n][chunk][slot][pix]
__device__ float g_red[(size_t)NB * 14 * HW];          // [n][slot][pix]
__device__ float g_w0[NB * HW];
__device__ float g_w1[NB * HW];
__device__ float g_w2[NB * HW];
__device__ float g_w3[NB * HW];
__device__ float g_cond[NB * HW];

__device__ __forceinline__ int iclamp(int v, int lo, int hi) {
    return v < lo ? lo : (v > hi ? hi : v);
}

__device__ __forceinline__ void cp_async16(void* dst, const void* src) {
    unsigned int da = (unsigned int)__cvta_generic_to_shared(dst);
    asm volatile("cp.async.cg.shared.global [%0], [%1], 16;" :: "r"(da), "l"(src));
}
__device__ __forceinline__ void cp_commit() {
    asm volatile("cp.async.commit_group;");
}
template <int N>
__device__ __forceinline__ void cp_wait() {
    asm volatile("cp.async.wait_group %0;" :: "n"(N));
}

// per-stage buffer: DSLICE prev halo slices + DSLICE cur tile slices
#define PREV_F (DSLICE * HALO * WW)     // 1792 floats
#define CUR_F  (DSLICE * TY * WW)       // 1024 floats
#define TOT_Q  ((PREV_F + CUR_F) / 4)   // 704 float4 per buffer

// ---------------------------------------------------------------------------
// Pass 1: cp.async double-buffered partial dot products over a D-chunk.
// grid (16 ytiles, 8 dchunks, 4 batch), block (64,4) = 256 thr
// ---------------------------------------------------------------------------
__global__ __launch_bounds__(256) void k_partial(const float* __restrict__ cur,
                                                 const float* __restrict__ prev) {
    __shared__ float sp[2][PREV_F];   // prev halos
    __shared__ float sc[2][CUR_F];    // cur tiles

    const int x   = threadIdx.x;
    const int ty  = threadIdx.y;
    const int y0  = blockIdx.x * TY;
    const int dch = blockIdx.y;
    const int n   = blockIdx.z;
    const int tid = ty * WW + x;

    const float* curB  = cur  + (size_t)n * DC * HW;
    const float* prevB = prev + (size_t)n * DC * HW;

    const int d0 = dch * DPER;

    // ---- staging lambda (as macro-style code) ----
    auto stage = [&](int b, int dbase) {
#pragma unroll
        for (int j = 0; j < 3; j++) {
            const int i = tid + j * 256;
            if (i < PREV_F / 4) {                    // prev: 448 float4
                const int s  = i / (HALO * 16);
                const int rm = i - s * (HALO * 16);
                const int r  = rm >> 4;
                const int c4 = rm & 15;
                const int gr = iclamp(y0 - 1 + r, 0, HH - 1);
                cp_async16(&sp[b][s * (HALO * WW) + r * WW + c4 * 4],
                           prevB + (size_t)(dbase + s) * HW + gr * WW + c4 * 4);
            } else if (i < TOT_Q) {                  // cur: 256 float4
                const int k  = i - PREV_F / 4;
                const int s  = k >> 6;
                const int rm = k & 63;
                const int r  = rm >> 4;
                const int c4 = rm & 15;
                cp_async16(&sc[b][s * (TY * WW) + r * WW + c4 * 4],
                           curB + (size_t)(dbase + s) * HW + (y0 + r) * WW + c4 * 4);
            }
        }
        cp_commit();
    };

    // clamped column indices (row clamping baked into smem stage)
    const int xm  = x - 1 < 0 ? 0 : x - 1;
    const int xp1 = x + 1 > WW - 1 ? WW - 1 : x + 1;
    const int xp2 = x + 2 > WW - 1 ? WW - 1 : x + 2;
    const int rA = (ty    ) * WW;   // dy=-1
    const int rB = (ty + 1) * WW;   // dy= 0
    const int rC = (ty + 2) * WW;   // dy=+1
    const int rD = (ty + 3) * WW;   // dy=+2

    float acc[14];
#pragma unroll
    for (int k = 0; k < 14; k++) acc[k] = 0.f;

    stage(0, d0);

#pragma unroll 1
    for (int d4 = 0; d4 < DPER / DSLICE; d4++) {
        if (d4 + 1 < DPER / DSLICE) {
            stage((d4 + 1) & 1, d0 + (d4 + 1) * DSLICE);
            cp_wait<1>();
        } else {
            cp_wait<0>();
        }
        __syncthreads();

        const int b = d4 & 1;
#pragma unroll
        for (int s = 0; s < DSLICE; s++) {
            const float* P = sp[b] + s * (HALO * WW);
            const float  c = sc[b][s * (TY * WW) + tid];
            const float a0  = P[rA + xm];
            const float a1  = P[rA + x];
            const float a2  = P[rA + xp1];
            const float a3  = P[rB + xm];
            const float a4  = P[rB + x];
            const float a5  = P[rB + xp1];
            const float a6  = P[rC + xm];
            const float a7  = P[rC + x];
            const float a8  = P[rC + xp1];
            const float a9  = P[rA + xp2];
            const float a10 = P[rD + xm];
            const float a11 = P[rD + xp2];
            acc[0]  = fmaf(c, a0,  acc[0]);
            acc[1]  = fmaf(c, a1,  acc[1]);
            acc[2]  = fmaf(c, a2,  acc[2]);
            acc[3]  = fmaf(c, a3,  acc[3]);
            acc[4]  = fmaf(c, a4,  acc[4]);
            acc[5]  = fmaf(c, a5,  acc[5]);
            acc[6]  = fmaf(c, a6,  acc[6]);
            acc[7]  = fmaf(c, a7,  acc[7]);
            acc[8]  = fmaf(c, a8,  acc[8]);
            acc[9]  = fmaf(c, a9,  acc[9]);
            acc[10] = fmaf(c, a10, acc[10]);
            acc[11] = fmaf(c, a11, acc[11]);
            acc[12] = fmaf(c, c,   acc[12]);
            acc[13] = fmaf(a4, a4, acc[13]);
        }
        __syncthreads();
    }

    const int pix = (y0 + ty) * WW + x;
    float* o = g_part + (size_t)(n * DCH + dch) * 14 * HW + pix;
#pragma unroll
    for (int k = 0; k < 14; k++) o[(size_t)k * HW] = acc[k];
}

// ---------------------------------------------------------------------------
// Pass 2a: reduce the 8 D-chunks. float4 over pixels; fully coalesced.
// threads = NB*14*HW/4 = 57344
// ---------------------------------------------------------------------------
__global__ __launch_bounds__(256) void k_reduce() {
    const int t    = blockIdx.x * blockDim.x + threadIdx.x;
    const int n    = t / (14 * 1024);
    const int r    = t - n * (14 * 1024);
    const int slot = r >> 10;
    const int p4   = (r & 1023) << 2;

    float4 a = make_float4(0.f, 0.f, 0.f, 0.f);
#pragma unroll
    for (int c = 0; c < DCH; c++) {
        const float4 v = *(const float4*)&g_part[(((size_t)(n * DCH + c)) * 14 + slot) * HW + p4];
        a.x += v.x; a.y += v.y; a.z += v.z; a.w += v.w;
    }
    *(float4*)&g_red[((size_t)n * 14 + slot) * HW + p4] = a;
}

// ---------------------------------------------------------------------------
// Pass 2b: cosine affinity -> mass/cond + 4 agg weights (g_red is L2-hot).
// grid (16, NB), block (64, 4)
// ---------------------------------------------------------------------------
__global__ __launch_bounds__(256) void k_weights() {
    __shared__ float s_pn[HALO * WW];

    const int x   = threadIdx.x;
    const int ty  = threadIdx.y;
    const int y0  = blockIdx.x * TY;
    const int n   = blockIdx.y;
    const int tid = ty * WW + x;

    const float* base = g_red + (size_t)n * 14 * HW;

    // halo prev-norms (slot 13)
    for (int i = tid; i < HALO * WW; i += 256) {
        const int r  = i >> 6;
        const int cc = i & (WW - 1);
        const int gr = iclamp(y0 - 1 + r, 0, HH - 1);
        s_pn[i] = sqrtf(base[(size_t)13 * HW + gr * WW + cc]) + 1e-8f;
    }
    __syncthreads();

    const int y   = y0 + ty;
    const int pix = y * WW + x;

    float acc[13];
#pragma unroll
    for (int k = 0; k < 13; k++) acc[k] = base[(size_t)k * HW + pix];

    const float invcn = 1.f / (sqrtf(acc[12]) + 1e-8f);

    float aff[NOFF];
#pragma unroll
    for (int k = 0; k < NOFF; k++) {
        const int py = y + c_dy[k];
        const int px = x + c_dx[k];
        const bool valid = (py >= 0) & (py < HH) & (px >= 0) & (px < WW);
        const int lr = ty + c_dy[k] + 1;
        const int lc = iclamp(px, 0, WW - 1);
        const float pn = s_pn[lr * WW + lc];
        float a = acc[k] * invcn / pn;
        a = fmaxf(a, 0.f);
        aff[k] = valid ? a : 0.f;
    }

    float mass = 0.f;
#pragma unroll
    for (int k = 0; k < 9; k++) mass += aff[k];

    const bool  cond = (mass > -10.f) && (mass < 10.f);
    const float inv  = 1.f / (mass > 0.f ? mass : 1.f);

    const int t = n * HW + pix;
    g_w0[t]   = aff[0]  > 0.f ? aff[0]  * inv : 0.f;  // (-1,-1)
    g_w1[t]   = aff[9]  > 0.f ? aff[9]  * inv : 0.f;  // (-1,+2)
    g_w2[t]   = aff[10] > 0.f ? aff[10] * inv : 0.f;  // (+2,-1)
    g_w3[t]   = aff[11] > 0.f ? aff[11] * inv : 0.f;  // (+2,+2)
    g_cond[t] = cond ? 1.f : 0.f;
}

// ---------------------------------------------------------------------------
// Pass 3: out = cond * (mem + (d>0) * sum_k w_k * mem[off_k]); 4 pixels/thread.
// ---------------------------------------------------------------------------
__global__ __launch_bounds__(256) void k_output(const float* __restrict__ mem,
                                                float* __restrict__ out) {
    const int tid = blockIdx.x * blockDim.x + threadIdx.x;
    const int pg  = tid & 1023;
    const int nd  = tid >> 10;              // uniform per block
    const int d   = nd & (DC - 1);
    const int n   = nd >> 8;
    const int y   = pg >> 4;
    const int x0  = (pg & 15) << 2;

    const int np = n * HW + y * WW + x0;
    const float4 cond = *(const float4*)&g_cond[np];
    const float4 w0   = *(const float4*)&g_w0[np];
    const float4 w1   = *(const float4*)&g_w1[np];
    const float4 w2   = *(const float4*)&g_w2[np];
    const float4 w3   = *(const float4*)&g_w3[np];

    const float* mp = mem + (size_t)nd * HW;
    float4 v = *(const float4*)&mp[y * WW + x0];

    if (d != 0) {   // uniform per block
        const int ym = y - 1 < 0 ? 0 : y - 1;
        const int yp = y + 2 > HH - 1 ? HH - 1 : y + 2;
        const float* ru = mp + ym * WW;
        const float* rd = mp + yp * WW;

        const float4 Au = *(const float4*)&ru[x0];
        const float4 Ad = *(const float4*)&rd[x0];
        const float Lu = (x0 == 0) ? Au.x : ru[x0 - 1];
        const float Ld = (x0 == 0) ? Ad.x : rd[x0 - 1];
        float2 Ru, Rd;
        if (x0 < WW - 4) {
            Ru = *(const float2*)&ru[x0 + 4];
            Rd = *(const float2*)&rd[x0 + 4];
        } else {
            Ru = make_float2(Au.w, Au.w);
            Rd = make_float2(Ad.w, Ad.w);
        }

        v.x = fmaf(w0.x, Lu,   fmaf(w1.x, Au.z, fmaf(w2.x, Ld,   fmaf(w3.x, Ad.z, v.x))));
        v.y = fmaf(w0.y, Au.x, fmaf(w1.y, Au.w, fmaf(w2.y, Ad.x, fmaf(w3.y, Ad.w, v.y))));
        v.z = fmaf(w0.z, Au.y, fmaf(w1.z, Ru.x, fmaf(w2.z, Ad.y, fmaf(w3.z, Rd.x, v.z))));
        v.w = fmaf(w0.w, Au.z, fmaf(w1.w, Ru.y, fmaf(w2.w, Ad.z, fmaf(w3.w, Rd.y, v.w))));
    }

    v.x = cond.x != 0.f ? v.x : 0.f;
    v.y = cond.y != 0.f ? v.y : 0.f;
    v.z = cond.z != 0.f ? v.z : 0.f;
    v.w = cond.w != 0.f ? v.w : 0.f;

    *(float4*)&out[(size_t)nd * HW + y * WW + x0] = v;
}

// ---------------------------------------------------------------------------
extern "C" void kernel_launch(void* const* d_in, const int* in_sizes, int n_in,
                              void* d_out, int out_size) {
    const float* cur  = (const float*)d_in[0];
    const float* prev = (const float*)d_in[1];
    const float* mem  = (const float*)d_in[2];
    float* out = (float*)d_out;

    k_partial<<<dim3(HH / TY, DCH, NB), dim3(WW, TY)>>>(cur, prev);
    k_reduce<<<(NB * 14 * HW / 4) / 256, 256>>>();
    k_weights<<<dim3(HH / TY, NB), dim3(WW, TY)>>>();
    k_output<<<(NB * DC * HW / 4) / 256, 256>>>(mem, out);
}

// round 4
// speedup vs baseline: 1.4164x; 1.1240x over previous
#include <cuda_runtime.h>

#define NB   4
#define DC   256
#define HH   64
#define WW   64
#define HW   4096
#define DCH  8        // chunks over D
#define DPER 32       // D per chunk
#define NOFF 12
#define TY   4        // rows per tile
#define HALO 7        // TY + 3 halo rows (dy in -1..2)
#define DSLICE 4      // d-slices per pipeline stage

// offset order: 3x3 window row-major (idx 4 = (0,0)), then (-1,2),(2,-1),(2,2).
__device__ __constant__ int c_dy[NOFF] = {-1,-1,-1, 0,0,0, 1,1,1, -1, 2, 2};
__device__ __constant__ int c_dx[NOFF] = {-1, 0, 1,-1,0,1,-1,0,1,  2,-1, 2};

// scratch (no allocations allowed)
__device__ __align__(16) float g_part[(size_t)NB * DCH * 14 * HW];
__device__ __align__(16) float g_red[(size_t)NB * 14 * HW];
__device__ __align__(16) float g_w0[NB * HW];
__device__ __align__(16) float g_w1[NB * HW];
__device__ __align__(16) float g_w2[NB * HW];
__device__ __align__(16) float g_w3[NB * HW];
__device__ __align__(16) float g_cond[NB * HW];

__device__ __forceinline__ int iclamp(int v, int lo, int hi) {
    return v < lo ? lo : (v > hi ? hi : v);
}

__device__ __forceinline__ void cp_async16(void* dst, const void* src) {
    unsigned int da = (unsigned int)__cvta_generic_to_shared(dst);
    asm volatile("cp.async.cg.shared.global [%0], [%1], 16;" :: "r"(da), "l"(src));
}
__device__ __forceinline__ void cp_commit() {
    asm volatile("cp.async.commit_group;");
}
template <int N>
__device__ __forceinline__ void cp_wait() {
    asm volatile("cp.async.wait_group %0;" :: "n"(N));
}

#define PREV_F (DSLICE * HALO * WW)     // 1792 floats
#define CUR_F  (DSLICE * TY * WW)       // 1024 floats
#define TOT_Q  ((PREV_F + CUR_F) / 4)   // 704 float4 per buffer

// ---------------------------------------------------------------------------
// Pass 1: cp.async double-buffered, 2 pixels/thread with vector LDS.
// grid (16 ytiles, 8 dchunks, 4 batch), block (32, 4) = 128 thr
// ---------------------------------------------------------------------------
__global__ __launch_bounds__(128) void k_partial(const float* __restrict__ cur,
                                                 const float* __restrict__ prev) {
    __shared__ float sp[2][PREV_F];
    __shared__ float sc[2][CUR_F];

    const int tx  = threadIdx.x;           // 0..31 -> pixels 2tx, 2tx+1
    const int ty  = threadIdx.y;           // 0..3
    const int y0  = blockIdx.x * TY;
    const int dch = blockIdx.y;
    const int n   = blockIdx.z;
    const int tid = ty * 32 + tx;          // 0..127
    const int x0  = tx * 2;

    const float* curB  = cur  + (size_t)n * DC * HW;
    const float* prevB = prev + (size_t)n * DC * HW;
    const int d0 = dch * DPER;

    auto stage = [&](int b, int dbase) {
#pragma unroll
        for (int j = 0; j < 6; j++) {
            const int i = tid + j * 128;
            if (i < PREV_F / 4) {                    // prev: 448 float4
                const int s  = i / (HALO * 16);
                const int rm = i - s * (HALO * 16);
                const int r  = rm >> 4;
                const int c4 = rm & 15;
                const int gr = iclamp(y0 - 1 + r, 0, HH - 1);
                cp_async16(&sp[b][s * (HALO * WW) + r * WW + c4 * 4],
                           prevB + (size_t)(dbase + s) * HW + gr * WW + c4 * 4);
            } else if (i < TOT_Q) {                  // cur: 256 float4
                const int k  = i - PREV_F / 4;
                const int s  = k >> 6;
                const int rm = k & 63;
                const int r  = rm >> 4;
                const int c4 = rm & 15;
                cp_async16(&sc[b][s * (TY * WW) + r * WW + c4 * 4],
                           curB + (size_t)(dbase + s) * HW + (y0 + r) * WW + c4 * 4);
            }
        }
        cp_commit();
    };

    const int rA = (ty    ) * WW;   // dy=-1
    const int rB = (ty + 1) * WW;   // dy= 0
    const int rC = (ty + 2) * WW;   // dy=+1
    const int rD = (ty + 3) * WW;   // dy=+2
    const int xl  = x0 == 0 ? 0 : x0 - 1;     // clamped left
    const int xr2 = x0 + 2 > WW - 1 ? WW - 1 : x0 + 2;
    const bool lastx = (tx == 31);

    float2 acc[14];
#pragma unroll
    for (int k = 0; k < 14; k++) acc[k] = make_float2(0.f, 0.f);

    stage(0, d0);

#pragma unroll 1
    for (int d4 = 0; d4 < DPER / DSLICE; d4++) {
        if (d4 + 1 < DPER / DSLICE) {
            stage((d4 + 1) & 1, d0 + (d4 + 1) * DSLICE);
            cp_wait<1>();
        } else {
            cp_wait<0>();
        }
        __syncthreads();

        const int b = d4 & 1;
#pragma unroll
        for (int s = 0; s < DSLICE; s++) {
            const float* P = sp[b] + s * (HALO * WW);
            const float2 c2 = *(const float2*)&sc[b][s * (TY * WW) + ty * WW + x0];

            const float2 A0 = *(const float2*)&P[rA + x0];
            const float2 B0 = *(const float2*)&P[rB + x0];
            const float2 C0 = *(const float2*)&P[rC + x0];
            const float2 D0 = *(const float2*)&P[rD + x0];
            const float  AL = P[rA + xl];
            const float  BL = P[rB + xl];
            const float  CL = P[rC + xl];
            const float  DL = P[rD + xl];
            const float2 A1 = lastx ? make_float2(A0.y, A0.y)
                                    : *(const float2*)&P[rA + x0 + 2];
            const float2 D1 = lastx ? make_float2(D0.y, D0.y)
                                    : *(const float2*)&P[rD + x0 + 2];
            const float  B2 = P[rB + xr2];
            const float  C2 = P[rC + xr2];

            const float c0 = c2.x, c1 = c2.y;
            acc[0].x  = fmaf(c0, AL,   acc[0].x);   acc[0].y  = fmaf(c1, A0.x, acc[0].y);
            acc[1].x  = fmaf(c0, A0.x, acc[1].x);   acc[1].y  = fmaf(c1, A0.y, acc[1].y);
            acc[2].x  = fmaf(c0, A0.y, acc[2].x);   acc[2].y  = fmaf(c1, A1.x, acc[2].y);
            acc[3].x  = fmaf(c0, BL,   acc[3].x);   acc[3].y  = fmaf(c1, B0.x, acc[3].y);
            acc[4].x  = fmaf(c0, B0.x, acc[4].x);   acc[4].y  = fmaf(c1, B0.y, acc[4].y);
            acc[5].x  = fmaf(c0, B0.y, acc[5].x);   acc[5].y  = fmaf(c1, B2,   acc[5].y);
            acc[6].x  = fmaf(c0, CL,   acc[6].x);   acc[6].y  = fmaf(c1, C0.x, acc[6].y);
            acc[7].x  = fmaf(c0, C0.x, acc[7].x);   acc[7].y  = fmaf(c1, C0.y, acc[7].y);
            acc[8].x  = fmaf(c0, C0.y, acc[8].x);   acc[8].y  = fmaf(c1, C2,   acc[8].y);
            acc[9].x  = fmaf(c0, A1.x, acc[9].x);   acc[9].y  = fmaf(c1, A1.y, acc[9].y);
            acc[10].x = fmaf(c0, DL,   acc[10].x);  acc[10].y = fmaf(c1, D0.x, acc[10].y);
            acc[11].x = fmaf(c0, D1.x, acc[11].x);  acc[11].y = fmaf(c1, D1.y, acc[11].y);
            acc[12].x = fmaf(c0, c0,   acc[12].x);  acc[12].y = fmaf(c1, c1,   acc[12].y);
            acc[13].x = fmaf(B0.x, B0.x, acc[13].x);
            acc[13].y = fmaf(B0.y, B0.y, acc[13].y);
        }
        __syncthreads();
    }

    const int pix = (y0 + ty) * WW + x0;
    float* o = g_part + (size_t)(n * DCH + dch) * 14 * HW + pix;
#pragma unroll
    for (int k = 0; k < 14; k++) *(float2*)&o[(size_t)k * HW] = acc[k];
}

// ---------------------------------------------------------------------------
// Pass 2a: reduce 8 D-chunks, float4-coalesced.
// ---------------------------------------------------------------------------
__global__ __launch_bounds__(256) void k_reduce() {
    const int t    = blockIdx.x * blockDim.x + threadIdx.x;
    const int n    = t / (14 * 1024);
    const int r    = t - n * (14 * 1024);
    const int slot = r >> 10;
    const int p4   = (r & 1023) << 2;

    float4 a = make_float4(0.f, 0.f, 0.f, 0.f);
#pragma unroll
    for (int c = 0; c < DCH; c++) {
        const float4 v = *(const float4*)&g_part[(((size_t)(n * DCH + c)) * 14 + slot) * HW + p4];
        a.x += v.x; a.y += v.y; a.z += v.z; a.w += v.w;
    }
    *(float4*)&g_red[((size_t)n * 14 + slot) * HW + p4] = a;
}

// ---------------------------------------------------------------------------
// Pass 2b: cosine affinity -> mass/cond + 4 agg weights (g_red L2-hot).
// grid (16, NB), block (64, 4)
// ---------------------------------------------------------------------------
__global__ __launch_bounds__(256) void k_weights() {
    __shared__ float s_pn[HALO * WW];

    const int x   = threadIdx.x;
    const int ty  = threadIdx.y;
    const int y0  = blockIdx.x * TY;
    const int n   = blockIdx.y;
    const int tid = ty * WW + x;

    const float* base = g_red + (size_t)n * 14 * HW;

    for (int i = tid; i < HALO * WW; i += 256) {
        const int r  = i >> 6;
        const int cc = i & (WW - 1);
        const int gr = iclamp(y0 - 1 + r, 0, HH - 1);
        s_pn[i] = sqrtf(base[(size_t)13 * HW + gr * WW + cc]) + 1e-8f;
    }
    __syncthreads();

    const int y   = y0 + ty;
    const int pix = y * WW + x;

    float acc[13];
#pragma unroll
    for (int k = 0; k < 13; k++) acc[k] = base[(size_t)k * HW + pix];

    const float invcn = 1.f / (sqrtf(acc[12]) + 1e-8f);

    float aff[NOFF];
#pragma unroll
    for (int k = 0; k < NOFF; k++) {
        const int py = y + c_dy[k];
        const int px = x + c_dx[k];
        const bool valid = (py >= 0) & (py < HH) & (px >= 0) & (px < WW);
        const int lr = ty + c_dy[k] + 1;
        const int lc = iclamp(px, 0, WW - 1);
        const float pn = s_pn[lr * WW + lc];
        float a = acc[k] * invcn / pn;
        a = fmaxf(a, 0.f);
        aff[k] = valid ? a : 0.f;
    }

    float mass = 0.f;
#pragma unroll
    for (int k = 0; k < 9; k++) mass += aff[k];

    const bool  cond = (mass > -10.f) && (mass < 10.f);
    const float inv  = 1.f / (mass > 0.f ? mass : 1.f);

    const int t = n * HW + pix;
    g_w0[t]   = aff[0]  > 0.f ? aff[0]  * inv : 0.f;  // (-1,-1)
    g_w1[t]   = aff[9]  > 0.f ? aff[9]  * inv : 0.f;  // (-1,+2)
    g_w2[t]   = aff[10] > 0.f ? aff[10] * inv : 0.f;  // (+2,-1)
    g_w3[t]   = aff[11] > 0.f ? aff[11] * inv : 0.f;  // (+2,+2)
    g_cond[t] = cond ? 1.f : 0.f;
}

// ---------------------------------------------------------------------------
// Pass 3: 4 pixels x 2 d-planes per thread -> weights amortized, MLP ~19.
// threads = NB*DC*HW/8 = 524288; d uniform per block.
// ---------------------------------------------------------------------------
__device__ __forceinline__ float4 proc_plane(const float* __restrict__ mp,
                                             int y, int x0, bool do_agg,
                                             float4 w0, float4 w1,
                                             float4 w2, float4 w3) {
    float4 v = *(const float4*)&mp[y * WW + x0];
    if (do_agg) {
        const int ym = y - 1 < 0 ? 0 : y - 1;
        const int yp = y + 2 > HH - 1 ? HH - 1 : y + 2;
        const float* ru = mp + ym * WW;
        const float* rd = mp + yp * WW;

        const float4 Au = *(const float4*)&ru[x0];
        const float4 Ad = *(const float4*)&rd[x0];
        const float Lu = (x0 == 0) ? Au.x : ru[x0 - 1];
        const float Ld = (x0 == 0) ? Ad.x : rd[x0 - 1];
        float2 Ru, Rd;
        if (x0 < WW - 4) {
            Ru = *(const float2*)&ru[x0 + 4];
            Rd = *(const float2*)&rd[x0 + 4];
        } else {
            Ru = make_float2(Au.w, Au.w);
            Rd = make_float2(Ad.w, Ad.w);
        }
        v.x = fmaf(w0.x, Lu,   fmaf(w1.x, Au.z, fmaf(w2.x, Ld,   fmaf(w3.x, Ad.z, v.x))));
        v.y = fmaf(w0.y, Au.x, fmaf(w1.y, Au.w, fmaf(w2.y, Ad.x, fmaf(w3.y, Ad.w, v.y))));
        v.z = fmaf(w0.z, Au.y, fmaf(w1.z, Ru.x, fmaf(w2.z, Ad.y, fmaf(w3.z, Rd.x, v.z))));
        v.w = fmaf(w0.w, Au.z, fmaf(w1.w, Ru.y, fmaf(w2.w, Ad.z, fmaf(w3.w, Rd.y, v.w))));
    }
    return v;
}

__global__ __launch_bounds__(256) void k_output(const float* __restrict__ mem,
                                                float* __restrict__ out) {
    const int t    = blockIdx.x * blockDim.x + threadIdx.x;
    const int pg   = t & 1023;          // pixel group (4 px)
    const int rest = t >> 10;
    const int dp   = rest & 127;        // d-pair, uniform per block
    const int n    = rest >> 7;
    const int y    = pg >> 4;
    const int x0   = (pg & 15) << 2;

    const int np = n * HW + y * WW + x0;
    const float4 cond = *(const float4*)&g_cond[np];
    const float4 w0   = *(const float4*)&g_w0[np];
    const float4 w1   = *(const float4*)&g_w1[np];
    const float4 w2   = *(const float4*)&g_w2[np];
    const float4 w3   = *(const float4*)&g_w3[np];

    const size_t nd0 = (size_t)(n * DC + dp * 2);
    const float* mp0 = mem + nd0 * HW;
    const float* mp1 = mp0 + HW;

    float4 v0 = proc_plane(mp0, y, x0, dp != 0, w0, w1, w2, w3);
    float4 v1 = proc_plane(mp1, y, x0, true,    w0, w1, w2, w3);

    v0.x = cond.x != 0.f ? v0.x : 0.f;  v1.x = cond.x != 0.f ? v1.x : 0.f;
    v0.y = cond.y != 0.f ? v0.y : 0.f;  v1.y = cond.y != 0.f ? v1.y : 0.f;
    v0.z = cond.z != 0.f ? v0.z : 0.f;  v1.z = cond.z != 0.f ? v1.z : 0.f;
    v0.w = cond.w != 0.f ? v0.w : 0.f;  v1.w = cond.w != 0.f ? v1.w : 0.f;

    *(float4*)&out[nd0 * HW + y * WW + x0]        = v0;
    *(float4*)&out[(nd0 + 1) * HW + y * WW + x0]  = v1;
}

// ---------------------------------------------------------------------------
extern "C" void kernel_launch(void* const* d_in, const int* in_sizes, int n_in,
                              void* d_out, int out_size) {
    const float* cur  = (const float*)d_in[0];
    const float* prev = (const float*)d_in[1];
    const float* mem  = (const float*)d_in[2];
    float* out = (float*)d_out;

    k_partial<<<dim3(HH / TY, DCH, NB), dim3(32, TY)>>>(cur, prev);
    k_reduce<<<(NB * 14 * HW / 4) / 256, 256>>>();
    k_weights<<<dim3(HH / TY, NB), dim3(WW, TY)>>>();
    k_output<<<(NB * DC * HW / 8) / 256, 256>>>(mem, out);
}